// round 11
// baseline (speedup 1.0000x reference)
#include <cuda_runtime.h>
#include <cuda_bf16.h>

#define NPTS 1024
#define KPOS 512
#define KSEL 32
#define FULLMASK 0xFFFFFFFFu

typedef unsigned long long ull;

// scratch: compacted selected points per submap (x,y,z,idx-bits) + FPS seed slot
__device__ float4 g_pts[2048 * KPOS];
__device__ int    g_seed[2048];

// ---- packed f32x2 helpers (lanewise IEEE rn — bit-identical to scalar rn ops)
__device__ __forceinline__ ull pk2(float a, float b) {
    ull r; asm("mov.b64 %0, {%1, %2};" : "=l"(r) : "f"(a), "f"(b)); return r;
}
__device__ __forceinline__ void upk2(ull v, float& a, float& b) {
    asm("mov.b64 {%0, %1}, %2;" : "=f"(a), "=f"(b) : "l"(v));
}
__device__ __forceinline__ ull addx2(ull a, ull b) {
    ull r; asm("add.rn.f32x2 %0, %1, %2;" : "=l"(r) : "l"(a), "l"(b)); return r;
}
__device__ __forceinline__ ull subx2(ull a, ull b) {
    ull r; asm("sub.rn.f32x2 %0, %1, %2;" : "=l"(r) : "l"(a), "l"(b)); return r;
}
__device__ __forceinline__ ull mulx2(ull a, ull b) {
    ull r; asm("mul.rn.f32x2 %0, %1, %2;" : "=l"(r) : "l"(a), "l"(b)); return r;
}

// ============================================================================
// Kernel 1 (select v5): 512 threads, 2 points/thread. Unique 42-bit key
// (dist_bits<<10 | index); jax top_k(-dist) tie semantics == key <= bound.
// One 11-bit histogram pass typically; exact boundary on <=64 candidates.
// ============================================================================
__global__ __launch_bounds__(512, 4)
void select_kernel(const float* __restrict__ pos)
{
    __shared__ unsigned int hist[2048];
    __shared__ ull  sPrefix;
    __shared__ unsigned int sKth, sCnt;
    __shared__ int  sShift;
    __shared__ ull  cand[64];
    __shared__ unsigned int ccnt;
    __shared__ ull  sBound;
    __shared__ unsigned int wS[16];
    __shared__ ull  wpk[16];
    __shared__ ull  spk;

    const int t = threadIdx.x;
    const int w = t >> 5, lane = t & 31;
    const int b = blockIdx.x;
    const long base = (long)b * NPTS;

    if (t == 0) { sPrefix = 0ull; sKth = KPOS; ccnt = 0u; }

    // ---- load 2 points (indices 2t, 2t+1) via three float2 ----
    const float2* p2 = (const float2*)(pos + 3 * base + 6 * t);
    const float2 v0 = p2[0], v1 = p2[1], v2 = p2[2];
    const float pxa = v0.x, pya = v0.y, pza = v1.x;
    const float pxb = v1.y, pyb = v2.x, pzb = v2.y;
    const int ia = 2 * t, ib = 2 * t + 1;

    const unsigned int kbA =
        __float_as_uint(__fsqrt_rn(__fadd_rn(__fmul_rn(pxa,pxa), __fmul_rn(pya,pya))));
    const unsigned int kbB =
        __float_as_uint(__fsqrt_rn(__fadd_rn(__fmul_rn(pxb,pxb), __fmul_rn(pyb,pyb))));
    const ull keyA = (((ull)kbA) << 10) | (unsigned int)ia;
    const ull keyB = (((ull)kbB) << 10) | (unsigned int)ib;

    // ---- iterative radix narrowing with early exit ----
    {
        const int shifts[4] = {31, 20, 9, 0};
        const int bitsv [4] = {11, 11, 11, 9};
        #pragma unroll 1
        for (int p = 0; p < 4; p++) {
            const int shift = shifts[p];
            ((uint4*)hist)[t] = make_uint4(0u, 0u, 0u, 0u);
            __syncthreads();
            const ull prefix = sPrefix;
            const unsigned int kth = sKth;
            const ull mhi = ~((1ull << (shift + bitsv[p])) - 1ull);
            const unsigned int dm = (1u << bitsv[p]) - 1u;
            if ((keyA & mhi) == prefix)
                atomicAdd(&hist[(unsigned int)(keyA >> shift) & dm], 1u);
            if ((keyB & mhi) == prefix)
                atomicAdd(&hist[(unsigned int)(keyB >> shift) & dm], 1u);
            __syncthreads();

            const unsigned int h0 = hist[4*t], h1 = hist[4*t+1],
                               h2 = hist[4*t+2], h3 = hist[4*t+3];
            const unsigned int s = h0 + h1 + h2 + h3;
            unsigned int inc = s;
            #pragma unroll
            for (int d = 1; d < 32; d <<= 1) {
                unsigned int v = __shfl_up_sync(FULLMASK, inc, d);
                if (lane >= d) inc += v;
            }
            if (lane == 31) wS[w] = inc;
            __syncthreads();
            if (t < 32) {
                unsigned int wv = (t < 16) ? wS[t] : 0u;
                unsigned int winc = wv;
                #pragma unroll
                for (int d = 1; d < 32; d <<= 1) {
                    unsigned int v = __shfl_up_sync(FULLMASK, winc, d);
                    if (t >= d) winc += v;
                }
                if (t < 16) wS[t] = winc - wv;
            }
            __syncthreads();
            unsigned int c = wS[w] + (inc - s);
            const unsigned int hv[4] = {h0, h1, h2, h3};
            #pragma unroll
            for (int i = 0; i < 4; i++) {
                if (kth > c && kth <= c + hv[i]) {
                    sPrefix = prefix | (((ull)(4 * t + i)) << shift);
                    sKth = kth - c;
                    sCnt = hv[i];
                    sShift = shift;
                }
                c += hv[i];
            }
            __syncthreads();
            if (sCnt <= 64u) break;
        }
    }

    // ---- exact boundary on <=64 candidates ----
    {
        const int fsh = sShift;
        const ull fpre = sPrefix;
        const ull mlo = ~((1ull << fsh) - 1ull);
        if ((keyA & mlo) == fpre) cand[atomicAdd(&ccnt, 1u)] = keyA;
        if ((keyB & mlo) == fpre) cand[atomicAdd(&ccnt, 1u)] = keyB;
        __syncthreads();
        const unsigned int fcnt = ccnt;
        const unsigned int fr = sKth;
        if (t < (int)fcnt) {
            const ull mine = cand[t];
            unsigned int rk = 0;
            for (unsigned int j = 0; j < fcnt; j++)
                rk += (cand[j] < mine) ? 1u : 0u;
            if (rk == fr - 1u) sBound = mine;
        }
        __syncthreads();
    }
    const bool selA = (keyA <= sBound);
    const bool selB = (keyB <= sBound);

    // ---- compaction (slot order == index order) + seed (block-min key) ----
    const unsigned int balA = __ballot_sync(FULLMASK, selA);
    const unsigned int balB = __ballot_sync(FULLMASK, selB);
    if (lane == 0) wS[w] = __popc(balA) + __popc(balB);

    ull pk = (keyA < keyB) ? keyA : keyB;
    #pragma unroll
    for (int off = 16; off > 0; off >>= 1) {
        ull o2 = __shfl_xor_sync(FULLMASK, pk, off);
        if (o2 < pk) pk = o2;
    }
    if (lane == 0) wpk[w] = pk;
    __syncthreads();
    if (t < 32) {
        unsigned int a0 = (t < 16) ? wS[t] : 0u;
        unsigned int iaW = a0;
        #pragma unroll
        for (int d = 1; d < 32; d <<= 1) {
            unsigned int v = __shfl_up_sync(FULLMASK, iaW, d);
            if (t >= d) iaW += v;
        }
        if (t < 16) wS[t] = iaW - a0;

        ull v2m = (t < 16) ? wpk[t] : ~0ull;
        #pragma unroll
        for (int off = 16; off > 0; off >>= 1) {
            ull o2 = __shfl_xor_sync(FULLMASK, v2m, off);
            if (o2 < v2m) v2m = o2;
        }
        if (t == 0) spk = v2m;
    }
    __syncthreads();
    {
        const unsigned int lm = (1u << lane) - 1u;
        const int baseSlot = (int)(wS[w] + __popc(balA & lm) + __popc(balB & lm));
        if (selA) {
            g_pts[b * KPOS + baseSlot] = make_float4(pxa, pya, pza, __int_as_float(ia));
            if (keyA == spk) g_seed[b] = baseSlot;
        }
        if (selB) {
            const int slotB = baseSlot + (selA ? 1 : 0);
            g_pts[b * KPOS + slotB] = make_float4(pxb, pyb, pzb, __int_as_float(ib));
            if (keyB == spk) g_seed[b] = slotB;
        }
    }
}

// ---- argmax tournament tree (validated bit-exact): pairs (2i,2i+1) keep
// left=lower slot at every level, so ">=" reproduces lowest-slot ties.
__device__ __forceinline__ void argmax16(const float* md, int lane,
                                         float& best, int& bslot)
{
    float v8[8]; int s8[8];
    #pragma unroll
    for (int i = 0; i < 8; i++) {
        const bool c = md[2*i] >= md[2*i+1];
        v8[i] = c ? md[2*i] : md[2*i+1];
        s8[i] = (c ? (2*i) : (2*i+1)) * 32 + lane;
    }
    float v4[4]; int s4[4];
    #pragma unroll
    for (int i = 0; i < 4; i++) {
        const bool c = v8[2*i] >= v8[2*i+1];
        v4[i] = c ? v8[2*i] : v8[2*i+1];
        s4[i] = c ? s8[2*i] : s8[2*i+1];
    }
    float v2a[2]; int s2a[2];
    #pragma unroll
    for (int i = 0; i < 2; i++) {
        const bool c = v4[2*i] >= v4[2*i+1];
        v2a[i] = c ? v4[2*i] : v4[2*i+1];
        s2a[i] = c ? s4[2*i] : s4[2*i+1];
    }
    const bool c = v2a[0] >= v2a[1];
    best = c ? v2a[0] : v2a[1];
    bslot = c ? s2a[0] : s2a[1];
}

// ============================================================================
// Kernel 2 (fps v6): ONE warp per submap, 16 pts/lane in registers, packed
// f32x2 sub/mul/add updates, single-redux argmax fast path, per-lane MLP.
// ============================================================================
__global__ __launch_bounds__(128)
void fps_mlp_kernel(const float* __restrict__ x,
                    const float* __restrict__ W1, const float* __restrict__ b1,
                    const float* __restrict__ W2, const float* __restrict__ b2,
                    const float* __restrict__ W3, const float* __restrict__ b3,
                    float* __restrict__ out_w, float* __restrict__ out_i)
{
    __shared__ float4 qpos[4 * KPOS];
    __shared__ float sW1[512]; __shared__ float sb1[16];
    __shared__ float sW2[128]; __shared__ float sb2[8];
    __shared__ float sW3[8];   __shared__ float sb3v;

    const int tid = threadIdx.x;
    for (int i = tid; i < 512; i += 128) sW1[i] = W1[i];
    if (tid < 128) sW2[tid] = W2[tid];
    if (tid < 16)  sb1[tid] = b1[tid];
    if (tid < 8)   sb2[tid] = b2[tid];
    if (tid < 8)   sW3[tid] = W3[tid];
    if (tid == 0)  sb3v = b3[0];
    __syncthreads();

    const int w = tid >> 5, lane = tid & 31;
    const int b = blockIdx.x * 4 + w;

    const float4* bp = g_pts + (size_t)b * KPOS;
    float4* qp = qpos + w * KPOS;

    ull pxp[8], pyp[8], pzp[8];
    float md[16];
    #pragma unroll
    for (int k = 0; k < 8; k++) {
        const float4 v0 = bp[(2*k)     * 32 + lane];
        const float4 v1 = bp[(2*k + 1) * 32 + lane];
        qp[(2*k)     * 32 + lane] = v0;
        qp[(2*k + 1) * 32 + lane] = v1;
        pxp[k] = pk2(v0.x, v1.x);
        pyp[k] = pk2(v0.y, v1.y);
        pzp[k] = pk2(v0.z, v1.z);
    }
    __syncwarp();

    const int s0 = g_seed[b];
    float4 q = qp[s0];
    int mysel = s0;   // lane 'step' records the step'th selection; step 0 = seed

    {
        const ull qxx = pk2(q.x, q.x), qyy = pk2(q.y, q.y), qzz = pk2(q.z, q.z);
        #pragma unroll
        for (int k = 0; k < 8; k++) {
            const ull dx = subx2(pxp[k], qxx);
            const ull dy = subx2(pyp[k], qyy);
            const ull dz = subx2(pzp[k], qzz);
            const ull d2 = addx2(addx2(mulx2(dx,dx), mulx2(dy,dy)), mulx2(dz,dz));
            upk2(d2, md[2*k], md[2*k+1]);
        }
    }

    #pragma unroll 1
    for (int step = 1; step < KSEL; step++) {
        float best; int bs;
        argmax16(md, lane, best, bs);
        const unsigned int bb = __float_as_uint(best);
        const unsigned int wm = __reduce_max_sync(FULLMASK, bb);
        const unsigned int mask = __ballot_sync(FULLMASK, bb == wm);
        int cur;
        if (__popc(mask) == 1) {
            // unique winner: broadcast its slot (1 redux + shfl on the chain)
            cur = __shfl_sync(FULLMASK, bs, __ffs(mask) - 1);
        } else {
            // exact tie across lanes (rare): lowest slot via redux.min
            const unsigned int cand2 = (bb == wm) ? (unsigned int)bs : 0xFFFFFFFFu;
            cur = (int)__reduce_min_sync(FULLMASK, cand2);
        }
        if (lane == step) mysel = cur;
        q = qp[cur];
        const ull qxx = pk2(q.x, q.x), qyy = pk2(q.y, q.y), qzz = pk2(q.z, q.z);
        #pragma unroll
        for (int k = 0; k < 8; k++) {
            const ull dx = subx2(pxp[k], qxx);
            const ull dy = subx2(pyp[k], qyy);
            const ull dz = subx2(pzp[k], qzz);
            const ull d2 = addx2(addx2(mulx2(dx,dx), mulx2(dy,dy)), mulx2(dz,dz));
            float a2, c2;
            upk2(d2, a2, c2);
            md[2*k]   = fminf(md[2*k],   a2);
            md[2*k+1] = fminf(md[2*k+1], c2);
        }
    }

    // ---- per-lane MLP (lane = selection step) ----
    const float4 qs = qp[mysel];
    const int o = __float_as_int(qs.w);
    const float* xr = x + ((long)b * NPTS + o) * 32;

    float h1[16];
    #pragma unroll
    for (int k2 = 0; k2 < 16; k2++) h1[k2] = sb1[k2];
    #pragma unroll
    for (int i = 0; i < 32; i += 4) {
        const float4 xv = *(const float4*)(xr + i);
        #pragma unroll
        for (int k2 = 0; k2 < 16; k2++) {
            h1[k2] = fmaf(xv.x, sW1[(i+0) * 16 + k2], h1[k2]);
            h1[k2] = fmaf(xv.y, sW1[(i+1) * 16 + k2], h1[k2]);
            h1[k2] = fmaf(xv.z, sW1[(i+2) * 16 + k2], h1[k2]);
            h1[k2] = fmaf(xv.w, sW1[(i+3) * 16 + k2], h1[k2]);
        }
    }
    #pragma unroll
    for (int k2 = 0; k2 < 16; k2++) h1[k2] = fmaxf(h1[k2], 0.f);

    float h2[8];
    #pragma unroll
    for (int k2 = 0; k2 < 8; k2++) h2[k2] = sb2[k2];
    #pragma unroll
    for (int j = 0; j < 16; j++) {
        const float hj = h1[j];
        #pragma unroll
        for (int k2 = 0; k2 < 8; k2++)
            h2[k2] = fmaf(hj, sW2[j * 8 + k2], h2[k2]);
    }
    float acc = sb3v;
    #pragma unroll
    for (int j = 0; j < 8; j++)
        acc = fmaf(fmaxf(h2[j], 0.f), sW3[j], acc);

    const float s = fmaxf(acc, 0.f) + log1pf(expf(-fabsf(acc)));

    out_w[b * KSEL + lane] = s;
    out_i[b * KSEL + lane] = (float)o;
}

extern "C" void kernel_launch(void* const* d_in, const int* in_sizes, int n_in,
                              void* d_out, int out_size)
{
    const float* x   = (const float*)d_in[0];
    const float* pos = (const float*)d_in[1];
    // d_in[2] = batch (unused; regular layout)
    const float* W1 = (const float*)d_in[3];
    const float* b1 = (const float*)d_in[4];
    const float* W2 = (const float*)d_in[5];
    const float* b2 = (const float*)d_in[6];
    const float* W3 = (const float*)d_in[7];
    const float* b3 = (const float*)d_in[8];

    const int B = in_sizes[2] / NPTS;   // 2048
    float* out_w = (float*)d_out;
    float* out_i = out_w + (size_t)B * KSEL;

    select_kernel<<<B, 512>>>(pos);
    fps_mlp_kernel<<<B / 4, 128>>>(x, W1, b1, W2, b2, W3, b3, out_w, out_i);
}